// round 8
// baseline (speedup 1.0000x reference)
#include <cuda_runtime.h>
#include <cuda_fp16.h>

#define NB 32
#define NN 1024
#define NM 1024
#define CSH8 6.104793232414985f   /* ln(448) */
#define THREADS 512
#define RANKS 8                    /* CTAs per cluster */
#define CLUSTERS 16                /* 2 batches each */

// Shared memory layout (bytes, dynamic):
#define OFF_K   0                        /* 128 rows x 1024 B fp8    = 131072 */
#define OFF_U   131072                   /* float u[128]             = 512    */
#define OFF_P   131584                   /* float p[1024] partial t  = 4096   */
#define OFF_VL  135680                   /* float vl[64][17] padded  = 4352   */
#define OFF_STG 140032                   /* float stg[8][1024]       = 32768  */
#define SMEM_TOTAL 172800

// ---- helpers ----------------------------------------------------------------
__device__ __forceinline__ unsigned smem_u32(const void* p) {
    unsigned r;
    asm("{ .reg .u64 t; cvta.to.shared.u64 t, %1; cvt.u32.u64 %0, t; }"
        : "=r"(r) : "l"(p));
    return r;
}
__device__ __forceinline__ unsigned mapa_rank(unsigned laddr, unsigned r) {
    unsigned a;
    asm("mapa.shared::cluster.u32 %0, %1, %2;" : "=r"(a) : "r"(laddr), "r"(r));
    return a;
}
__device__ __forceinline__ float ld_dsmem(unsigned a) {
    float v;
    asm volatile("ld.shared::cluster.f32 %0, [%1];" : "=f"(v) : "r"(a));
    return v;
}
__device__ __forceinline__ void st_dsmem(unsigned a, float v) {
    asm volatile("st.shared::cluster.f32 [%0], %1;" :: "r"(a), "f"(v) : "memory");
}
#define CLUSTER_SYNC() do { \
    asm volatile("barrier.cluster.arrive.aligned;" ::: "memory"); \
    asm volatile("barrier.cluster.wait.aligned;" ::: "memory"); \
} while (0)

__device__ __forceinline__ unsigned short pack_e4m3x2(float lo, float hi) {
    unsigned short r;
    asm("cvt.rn.satfinite.e4m3x2.f32 %0, %1, %2;" : "=h"(r) : "f"(hi), "f"(lo));
    return r;
}
// 4 packed e4m3 (byte0 = elem0) -> float4 (exact via fp16)
__device__ __forceinline__ float4 e4m3x4_to_float4(unsigned int w) {
    unsigned int h0, h1;
    asm("{\n\t.reg .b16 a, b;\n\t"
        "mov.b32 {a, b}, %2;\n\t"
        "cvt.rn.f16x2.e4m3x2 %0, a;\n\t"
        "cvt.rn.f16x2.e4m3x2 %1, b;\n\t}"
        : "=r"(h0), "=r"(h1) : "r"(w));
    __half2 H0 = *reinterpret_cast<__half2*>(&h0);
    __half2 H1 = *reinterpret_cast<__half2*>(&h1);
    float2 f0 = __half22float2(H0);
    float2 f1 = __half22float2(H1);
    return make_float4(f0.x, f0.y, f1.x, f1.y);
}

__global__ void k_zero(float* out) { *out = 0.0f; }

// ---------------------------------------------------------------------------
// Persistent Sinkhorn kernel. Cluster of 8 CTAs owns one batch at a time
// (rank r holds rows [r*128, r*128+128) of K in smem, fp8). 16 clusters, each
// processes batches {cid, cid+16}. All 20 iterations run out of SMEM.
// ---------------------------------------------------------------------------
__global__ __launch_bounds__(THREADS, 1) __cluster_dims__(RANKS, 1, 1)
void k_sink(const float4* __restrict__ D4, float* __restrict__ out) {
    extern __shared__ char smem[];
    unsigned sbase = smem_u32(smem);

    unsigned char* Ks = reinterpret_cast<unsigned char*>(smem) + OFF_K;
    float* U   = reinterpret_cast<float*>(smem + OFF_U);
    float* P   = reinterpret_cast<float*>(smem + OFF_P);
    float* Vl  = reinterpret_cast<float*>(smem + OFF_VL);   // [chunk 0..63][17]
    float* STG = reinterpret_cast<float*>(smem + OFF_STG);  // [8][1024]

    int tid = threadIdx.x;
    int w = tid >> 5, lane = tid & 31;
    unsigned rank;
    asm("mov.u32 %0, %%cluster_ctarank;" : "=r"(rank));
    int cid = blockIdx.x >> 3;

    float lsum = 0.0f;

    for (int bi = 0; bi < 2; ++bi) {
        int b = cid + bi * CLUSTERS;

        // ---- convert: 128 rows x 1024 cols of D -> fp8 in smem --------------
        const float4* Db = D4 + ((size_t)b * NN + rank * 128) * (NM / 4);
        for (int idx = tid; idx < 128 * 256; idx += THREADS) {
            float4 d = Db[idx];
            float e0 = __expf(fmaf(d.x, -10.0f, CSH8));
            float e1 = __expf(fmaf(d.y, -10.0f, CSH8));
            float e2 = __expf(fmaf(d.z, -10.0f, CSH8));
            float e3 = __expf(fmaf(d.w, -10.0f, CSH8));
            unsigned p01 = pack_e4m3x2(e0, e1);
            unsigned p23 = pack_e4m3x2(e2, e3);
            reinterpret_cast<unsigned*>(Ks)[idx] = p01 | (p23 << 16);
        }
        for (int c = tid; c < 64 * 17; c += THREADS) Vl[c] = 1.0f;  // v0 = 1
        __syncthreads();

        // ---- 20 Sinkhorn iterations ----------------------------------------
        for (int it = 0; it < 20; ++it) {
            // row phase: warp w -> rows w*8..w*8+7 ; u = 1/(K v)
            {
                const uint4* Kr = reinterpret_cast<const uint4*>(Ks + (size_t)w * 8 * 1024);
                float acc[8];
#pragma unroll
                for (int r = 0; r < 8; ++r) acc[r] = 0.0f;
#pragma unroll
                for (int ph = 0; ph < 2; ++ph) {
                    int q = ph * 32 + lane;
                    float vv[16];
#pragma unroll
                    for (int c = 0; c < 16; ++c) vv[c] = Vl[q * 17 + c];
#pragma unroll
                    for (int r = 0; r < 8; ++r) {
                        uint4 p = Kr[r * 64 + q];
                        float4 a = e4m3x4_to_float4(p.x);
                        float4 bb = e4m3x4_to_float4(p.y);
                        float4 c2 = e4m3x4_to_float4(p.z);
                        float4 d2 = e4m3x4_to_float4(p.w);
                        float s = acc[r];
                        s = fmaf(a.x,  vv[0],  s); s = fmaf(a.y,  vv[1],  s);
                        s = fmaf(a.z,  vv[2],  s); s = fmaf(a.w,  vv[3],  s);
                        s = fmaf(bb.x, vv[4],  s); s = fmaf(bb.y, vv[5],  s);
                        s = fmaf(bb.z, vv[6],  s); s = fmaf(bb.w, vv[7],  s);
                        s = fmaf(c2.x, vv[8],  s); s = fmaf(c2.y, vv[9],  s);
                        s = fmaf(c2.z, vv[10], s); s = fmaf(c2.w, vv[11], s);
                        s = fmaf(d2.x, vv[12], s); s = fmaf(d2.y, vv[13], s);
                        s = fmaf(d2.z, vv[14], s); s = fmaf(d2.w, vv[15], s);
                        acc[r] = s;
                    }
                }
#pragma unroll
                for (int r = 0; r < 8; ++r) {
                    float s = acc[r];
#pragma unroll
                    for (int o = 16; o > 0; o >>= 1)
                        s += __shfl_xor_sync(0xffffffffu, s, o);
                    if (lane == 0) U[w * 8 + r] = __fdividef(1.0f, s);
                }
            }
            __syncthreads();

            // col phase: group g (64 thr) -> rows g*16..+16; thread ct -> 16 cols
            {
                int g = tid >> 6, ct = tid & 63;
                const uint4* Kb =
                    reinterpret_cast<const uint4*>(Ks + (size_t)g * 16 * 1024) + ct;
                float4 A = {0,0,0,0}, B = {0,0,0,0}, C = {0,0,0,0}, E = {0,0,0,0};
#pragma unroll
                for (int i = 0; i < 16; ++i) {
                    float uu = U[g * 16 + i];
                    uint4 p = Kb[i * 64];
                    float4 x = e4m3x4_to_float4(p.x);
                    float4 y = e4m3x4_to_float4(p.y);
                    float4 z = e4m3x4_to_float4(p.z);
                    float4 t = e4m3x4_to_float4(p.w);
                    A.x = fmaf(x.x, uu, A.x); A.y = fmaf(x.y, uu, A.y);
                    A.z = fmaf(x.z, uu, A.z); A.w = fmaf(x.w, uu, A.w);
                    B.x = fmaf(y.x, uu, B.x); B.y = fmaf(y.y, uu, B.y);
                    B.z = fmaf(y.z, uu, B.z); B.w = fmaf(y.w, uu, B.w);
                    C.x = fmaf(z.x, uu, C.x); C.y = fmaf(z.y, uu, C.y);
                    C.z = fmaf(z.z, uu, C.z); C.w = fmaf(z.w, uu, C.w);
                    E.x = fmaf(t.x, uu, E.x); E.y = fmaf(t.y, uu, E.y);
                    E.z = fmaf(t.z, uu, E.z); E.w = fmaf(t.w, uu, E.w);
                }
                float4* st4 = reinterpret_cast<float4*>(&STG[g * 1024 + ct * 16]);
                st4[0] = A; st4[1] = B; st4[2] = C; st4[3] = E;
            }
            __syncthreads();

            // merge 8 group-partials -> P (thread owns 2 cols)
            {
                float p0 = 0.0f, p1 = 0.0f;
#pragma unroll
                for (int g2 = 0; g2 < 8; ++g2) {
                    p0 += STG[g2 * 1024 + 2 * tid];
                    p1 += STG[g2 * 1024 + 2 * tid + 1];
                }
                P[2 * tid]     = p0;
                P[2 * tid + 1] = p1;
            }
            CLUSTER_SYNC();   // all P vectors ready cluster-wide

            // slice reduce: rank owns cols [rank*128, rank*128+128)
            if (tid < 128) {
                int j = (int)rank * 128 + tid;
                float t = 0.0f;
#pragma unroll
                for (unsigned r2 = 0; r2 < RANKS; ++r2)
                    t += ld_dsmem(mapa_rank(sbase + OFF_P + j * 4, r2));
                float vj = __fdividef(1.0f, t);
                unsigned voff = sbase + OFF_VL + (((j >> 4) * 17) + (j & 15)) * 4;
#pragma unroll
                for (unsigned r2 = 0; r2 < RANKS; ++r2)
                    st_dsmem(mapa_rank(voff, r2), vj);
            }
            CLUSTER_SYNC();   // all Vl replicas updated
        }

        // ---- loss: sum over own rows of u_i * sum_j v_j K (ln448 - ln K) ----
        {
            const uint4* Kr = reinterpret_cast<const uint4*>(Ks + (size_t)w * 8 * 1024);
            float part[8];
#pragma unroll
            for (int r = 0; r < 8; ++r) part[r] = 0.0f;
#pragma unroll
            for (int ph = 0; ph < 2; ++ph) {
                int q = ph * 32 + lane;
                float vv[16];
#pragma unroll
                for (int c = 0; c < 16; ++c) vv[c] = Vl[q * 17 + c];
#pragma unroll
                for (int r = 0; r < 8; ++r) {
                    uint4 p = Kr[r * 64 + q];
                    float4 a = e4m3x4_to_float4(p.x);
                    float4 bb = e4m3x4_to_float4(p.y);
                    float4 c2 = e4m3x4_to_float4(p.z);
                    float4 d2 = e4m3x4_to_float4(p.w);
                    float s = part[r];
                    s = fmaf(a.x  * (CSH8 - __logf(a.x)),  vv[0],  s);
                    s = fmaf(a.y  * (CSH8 - __logf(a.y)),  vv[1],  s);
                    s = fmaf(a.z  * (CSH8 - __logf(a.z)),  vv[2],  s);
                    s = fmaf(a.w  * (CSH8 - __logf(a.w)),  vv[3],  s);
                    s = fmaf(bb.x * (CSH8 - __logf(bb.x)), vv[4],  s);
                    s = fmaf(bb.y * (CSH8 - __logf(bb.y)), vv[5],  s);
                    s = fmaf(bb.z * (CSH8 - __logf(bb.z)), vv[6],  s);
                    s = fmaf(bb.w * (CSH8 - __logf(bb.w)), vv[7],  s);
                    s = fmaf(c2.x * (CSH8 - __logf(c2.x)), vv[8],  s);
                    s = fmaf(c2.y * (CSH8 - __logf(c2.y)), vv[9],  s);
                    s = fmaf(c2.z * (CSH8 - __logf(c2.z)), vv[10], s);
                    s = fmaf(c2.w * (CSH8 - __logf(c2.w)), vv[11], s);
                    s = fmaf(d2.x * (CSH8 - __logf(d2.x)), vv[12], s);
                    s = fmaf(d2.y * (CSH8 - __logf(d2.y)), vv[13], s);
                    s = fmaf(d2.z * (CSH8 - __logf(d2.z)), vv[14], s);
                    s = fmaf(d2.w * (CSH8 - __logf(d2.w)), vv[15], s);
                    part[r] = s;
                }
            }
#pragma unroll
            for (int r = 0; r < 8; ++r) lsum += U[w * 8 + r] * part[r];
        }
        __syncthreads();   // K/Vl/U reuse safe for next batch (cluster-level
                           // hazards are covered by next batch's CLUSTER_SYNCs)
    }

    // ---- block reduction of loss, one atomic per CTA -------------------------
#pragma unroll
    for (int o = 16; o > 0; o >>= 1) lsum += __shfl_xor_sync(0xffffffffu, lsum, o);
    if (lane == 0) STG[w] = lsum;
    __syncthreads();
    if (tid == 0) {
        float t = 0.0f;
#pragma unroll
        for (int i = 0; i < THREADS / 32; ++i) t += STG[i];
        atomicAdd(out, t * (0.1f / (float)NB));
    }
}

// ---------------------------------------------------------------------------
extern "C" void kernel_launch(void* const* d_in, const int* in_sizes, int n_in,
                              void* d_out, int out_size) {
    const float4* D4 = reinterpret_cast<const float4*>(d_in[0]);
    float* out = reinterpret_cast<float*>(d_out);

    cudaFuncSetAttribute(k_sink, cudaFuncAttributeMaxDynamicSharedMemorySize,
                         SMEM_TOTAL);
    k_zero<<<1, 1>>>(out);
    k_sink<<<CLUSTERS * RANKS, THREADS, SMEM_TOTAL>>>(D4, out);
}

// round 9
// speedup vs baseline: 1.8425x; 1.8425x over previous
#include <cuda_runtime.h>
#include <cuda_fp16.h>

#define NB 32
#define NN 1024
#define NM 1024
#define CSH8 6.104793232414985f   /* ln(448) */
#define GCTAS 16                  /* CTAs per batch-group */
#define NITER 20

// K'' = 448*exp(-D/eps) as e4m3 fp8. 32 MB — L2-resident.
__device__ unsigned char g_K8[(size_t)NB * NN * NM];
__device__ float g_t[3][NB * NM];            // col-sum triple buffer
__device__ unsigned g_bar[NB * 32];          // per-batch epoch counter (128B stride)

// ---- fp8 helpers -----------------------------------------------------------
__device__ __forceinline__ unsigned short pack_e4m3x2(float lo, float hi) {
    unsigned short r;
    asm("cvt.rn.satfinite.e4m3x2.f32 %0, %1, %2;" : "=h"(r) : "f"(hi), "f"(lo));
    return r;
}
__device__ __forceinline__ float4 e4m3x4_to_float4(unsigned int w) {
    unsigned int h0, h1;
    asm("{\n\t.reg .b16 a, b;\n\t"
        "mov.b32 {a, b}, %2;\n\t"
        "cvt.rn.f16x2.e4m3x2 %0, a;\n\t"
        "cvt.rn.f16x2.e4m3x2 %1, b;\n\t}"
        : "=r"(h0), "=r"(h1) : "r"(w));
    __half2 H0 = *reinterpret_cast<__half2*>(&h0);
    __half2 H1 = *reinterpret_cast<__half2*>(&h1);
    float2 f0 = __half22float2(H0);
    float2 f1 = __half22float2(H1);
    return make_float4(f0.x, f0.y, f1.x, f1.y);
}
__device__ __forceinline__ float dot16(uint4 p, const float4& v0, const float4& v1,
                                       const float4& v2, const float4& v3, float s) {
    float4 a = e4m3x4_to_float4(p.x);
    float4 b = e4m3x4_to_float4(p.y);
    float4 c = e4m3x4_to_float4(p.z);
    float4 d = e4m3x4_to_float4(p.w);
    s = fmaf(a.x, v0.x, s); s = fmaf(a.y, v0.y, s);
    s = fmaf(a.z, v0.z, s); s = fmaf(a.w, v0.w, s);
    s = fmaf(b.x, v1.x, s); s = fmaf(b.y, v1.y, s);
    s = fmaf(b.z, v1.z, s); s = fmaf(b.w, v1.w, s);
    s = fmaf(c.x, v2.x, s); s = fmaf(c.y, v2.y, s);
    s = fmaf(c.z, v2.z, s); s = fmaf(c.w, v2.w, s);
    s = fmaf(d.x, v3.x, s); s = fmaf(d.y, v3.y, s);
    s = fmaf(d.z, v3.z, s); s = fmaf(d.w, v3.w, s);
    return s;
}

// CG-style 16-CTA epoch barrier: monotonic counter, no reset races.
__device__ __forceinline__ void group_barrier(unsigned* bar, unsigned target) {
    __syncthreads();
    if (threadIdx.x == 0) {
        asm volatile("fence.acq_rel.gpu;" ::: "memory");
        unsigned prev = atomicAdd(bar, 1u);
        if (prev + 1u < target) {
            unsigned v;
            do {
                asm volatile("ld.acquire.gpu.u32 %0, [%1];"
                             : "=r"(v) : "l"(bar) : "memory");
            } while (v < target);
        }
    }
    __syncthreads();
}

// ---------------------------------------------------------------------------
// Convert: K8 = e4m3(448*exp(-10D)); t[0]=1, t[1]=0, bar=0, out=0.
// ---------------------------------------------------------------------------
__global__ __launch_bounds__(256) void k_convert(const float4* __restrict__ D4,
                                                 float* __restrict__ out) {
    int idx = blockIdx.x * 256 + threadIdx.x;      // 0 .. 4194303
    float4 d0 = D4[2 * idx];
    float4 d1 = D4[2 * idx + 1];
    float e0 = __expf(fmaf(d0.x, -10.0f, CSH8));
    float e1 = __expf(fmaf(d0.y, -10.0f, CSH8));
    float e2 = __expf(fmaf(d0.z, -10.0f, CSH8));
    float e3 = __expf(fmaf(d0.w, -10.0f, CSH8));
    float e4 = __expf(fmaf(d1.x, -10.0f, CSH8));
    float e5 = __expf(fmaf(d1.y, -10.0f, CSH8));
    float e6 = __expf(fmaf(d1.z, -10.0f, CSH8));
    float e7 = __expf(fmaf(d1.w, -10.0f, CSH8));
    unsigned short p0 = pack_e4m3x2(e0, e1);
    unsigned short p1 = pack_e4m3x2(e2, e3);
    unsigned short p2 = pack_e4m3x2(e4, e5);
    unsigned short p3 = pack_e4m3x2(e6, e7);
    uint2 w;
    w.x = (unsigned int)p0 | ((unsigned int)p1 << 16);
    w.y = (unsigned int)p2 | ((unsigned int)p3 << 16);
    reinterpret_cast<uint2*>(g_K8)[idx] = w;

    if (idx < NB * NM) { g_t[0][idx] = 1.0f; g_t[1][idx] = 0.0f; }
    if (idx < NB * 32) g_bar[idx] = 0u;
    if (idx == 0) *out = 0.0f;
}

// ---------------------------------------------------------------------------
// Persistent Sinkhorn: grid 512 = 32 batches x 16 CTAs; CTA owns 64 rows.
// Per iteration: row phase (warp=8 rows, LDG.128, v reg-cached), col phase
// (thread=16 cols x 16 rows, smem merge, REDG), one group barrier.
// Loss computed in-kernel at the end.
// ---------------------------------------------------------------------------
__global__ __launch_bounds__(256, 4) void k_sink(float* __restrict__ out) {
    __shared__ float4 sv4[NM / 4];       // 4 KB  : v = 1/t
    __shared__ float  U[64];             // 256 B : u for this CTA's rows
    __shared__ float  stage[4][NM];      // 16 KB : col-phase merge

    int tid  = threadIdx.x;
    int w    = tid >> 5, lane = tid & 31;
    int b    = blockIdx.x >> 4;          // batch
    int rc   = blockIdx.x & 15;          // row-chunk: rows [rc*64, rc*64+64)
    unsigned* bar = &g_bar[b * 32];

    const unsigned char* Kcta = g_K8 + ((size_t)b * NN + rc * 64) * NM;

    for (int it = 0; it < NITER; ++it) {
        const float* tIn  = g_t[it % 3] + b * NM;
        float* tOut       = g_t[(it + 1) % 3] + b * NM;
        float* tZero      = g_t[(it + 2) % 3] + b * NM;

        // ---- row phase -----------------------------------------------------
        {
            float4 t4 = reinterpret_cast<const float4*>(tIn)[tid];
            sv4[tid] = make_float4(__fdividef(1.0f, t4.x), __fdividef(1.0f, t4.y),
                                   __fdividef(1.0f, t4.z), __fdividef(1.0f, t4.w));
            if (tid < 64) tZero[rc * 64 + tid] = 0.0f;   // 16 CTAs x 64 = 1024
            __syncthreads();

            const uint4* Kr = reinterpret_cast<const uint4*>(Kcta + (size_t)w * 8 * NM);
            float acc[8];
#pragma unroll
            for (int r = 0; r < 8; ++r) acc[r] = 0.0f;
#pragma unroll
            for (int ph = 0; ph < 2; ++ph) {
                int q = ph * 32 + lane;                  // uint4 idx 0..63
                float4 v0 = sv4[4 * q + 0];
                float4 v1 = sv4[4 * q + 1];
                float4 v2 = sv4[4 * q + 2];
                float4 v3 = sv4[4 * q + 3];
#pragma unroll
                for (int r = 0; r < 8; ++r) {
                    uint4 p = Kr[r * 64 + q];
                    acc[r] = dot16(p, v0, v1, v2, v3, acc[r]);
                }
            }
#pragma unroll
            for (int r = 0; r < 8; ++r) {
                float s = acc[r];
#pragma unroll
                for (int o = 16; o > 0; o >>= 1)
                    s += __shfl_xor_sync(0xffffffffu, s, o);
                if (lane == 0) U[w * 8 + r] = __fdividef(1.0f, s);
            }
            __syncthreads();
        }

        // ---- col phase -----------------------------------------------------
        {
            int cg = tid >> 6, ct = tid & 63;
            const uint4* Kb =
                reinterpret_cast<const uint4*>(Kcta + (size_t)cg * 16 * NM) + ct;
            float4 A = {0,0,0,0}, B = {0,0,0,0}, C = {0,0,0,0}, E = {0,0,0,0};
#pragma unroll
            for (int i = 0; i < 16; ++i) {
                float u = U[cg * 16 + i];
                uint4 p = Kb[i * (NM / 16)];
                float4 x = e4m3x4_to_float4(p.x);
                float4 y = e4m3x4_to_float4(p.y);
                float4 z = e4m3x4_to_float4(p.z);
                float4 t = e4m3x4_to_float4(p.w);
                A.x = fmaf(x.x, u, A.x); A.y = fmaf(x.y, u, A.y);
                A.z = fmaf(x.z, u, A.z); A.w = fmaf(x.w, u, A.w);
                B.x = fmaf(y.x, u, B.x); B.y = fmaf(y.y, u, B.y);
                B.z = fmaf(y.z, u, B.z); B.w = fmaf(y.w, u, B.w);
                C.x = fmaf(z.x, u, C.x); C.y = fmaf(z.y, u, C.y);
                C.z = fmaf(z.z, u, C.z); C.w = fmaf(z.w, u, C.w);
                E.x = fmaf(t.x, u, E.x); E.y = fmaf(t.y, u, E.y);
                E.z = fmaf(t.z, u, E.z); E.w = fmaf(t.w, u, E.w);
            }
            float4* st4 = reinterpret_cast<float4*>(&stage[cg][ct * 16]);
            st4[0] = A; st4[1] = B; st4[2] = C; st4[3] = E;
            __syncthreads();

            const float4* s0 = reinterpret_cast<const float4*>(stage[0]);
            const float4* s1 = reinterpret_cast<const float4*>(stage[1]);
            const float4* s2 = reinterpret_cast<const float4*>(stage[2]);
            const float4* s3 = reinterpret_cast<const float4*>(stage[3]);
            float4 r0 = s0[tid], r1 = s1[tid], r2 = s2[tid], r3 = s3[tid];
            float4 r;
            r.x = (r0.x + r1.x) + (r2.x + r3.x);
            r.y = (r0.y + r1.y) + (r2.y + r3.y);
            r.z = (r0.z + r1.z) + (r2.z + r3.z);
            r.w = (r0.w + r1.w) + (r2.w + r3.w);
            float* to = tOut + tid * 4;
            atomicAdd(to + 0, r.x);
            atomicAdd(to + 1, r.y);
            atomicAdd(to + 2, r.z);
            atomicAdd(to + 3, r.w);
        }

        // ---- group barrier (epoch it+1) -------------------------------------
        group_barrier(bar, (unsigned)(GCTAS * (it + 1)));
    }

    // ---- loss: (0.1/NB) * sum u_i v_j f (ln448 - ln f) over own 64 rows ------
    {
        const float* tIn = g_t[(NITER + 1) % 3] + b * NM;   // t[(19+1)%3] = t[2]... NITER%3? k=19 -> tOut=(20)%3=2
        // NITER = 20 -> final col output buffer index = NITER % 3? (19+1)%3 = 2.
        tIn = g_t[2] + b * NM;
        float4 t4 = reinterpret_cast<const float4*>(tIn)[tid];
        sv4[tid] = make_float4(__fdividef(1.0f, t4.x), __fdividef(1.0f, t4.y),
                               __fdividef(1.0f, t4.z), __fdividef(1.0f, t4.w));
        __syncthreads();

        const uint4* Kr = reinterpret_cast<const uint4*>(Kcta + (size_t)w * 8 * NM);
        float L = 0.0f;
#pragma unroll
        for (int ph = 0; ph < 2; ++ph) {
            int q = ph * 32 + lane;
            float4 v0 = sv4[4 * q + 0];
            float4 v1 = sv4[4 * q + 1];
            float4 v2 = sv4[4 * q + 2];
            float4 v3 = sv4[4 * q + 3];
#pragma unroll
            for (int r = 0; r < 8; ++r) {
                uint4 p = Kr[r * 64 + q];
                float4 a = e4m3x4_to_float4(p.x);
                float4 bb = e4m3x4_to_float4(p.y);
                float4 c = e4m3x4_to_float4(p.z);
                float4 d = e4m3x4_to_float4(p.w);
                float s = 0.0f;
                s = fmaf(a.x  * (CSH8 - __logf(a.x)),  v0.x, s);
                s = fmaf(a.y  * (CSH8 - __logf(a.y)),  v0.y, s);
                s = fmaf(a.z  * (CSH8 - __logf(a.z)),  v0.z, s);
                s = fmaf(a.w  * (CSH8 - __logf(a.w)),  v0.w, s);
                s = fmaf(bb.x * (CSH8 - __logf(bb.x)), v1.x, s);
                s = fmaf(bb.y * (CSH8 - __logf(bb.y)), v1.y, s);
                s = fmaf(bb.z * (CSH8 - __logf(bb.z)), v1.z, s);
                s = fmaf(bb.w * (CSH8 - __logf(bb.w)), v1.w, s);
                s = fmaf(c.x  * (CSH8 - __logf(c.x)),  v2.x, s);
                s = fmaf(c.y  * (CSH8 - __logf(c.y)),  v2.y, s);
                s = fmaf(c.z  * (CSH8 - __logf(c.z)),  v2.z, s);
                s = fmaf(c.w  * (CSH8 - __logf(c.w)),  v2.w, s);
                s = fmaf(d.x  * (CSH8 - __logf(d.x)),  v3.x, s);
                s = fmaf(d.y  * (CSH8 - __logf(d.y)),  v3.y, s);
                s = fmaf(d.z  * (CSH8 - __logf(d.z)),  v3.z, s);
                s = fmaf(d.w  * (CSH8 - __logf(d.w)),  v3.w, s);
                L = fmaf(U[w * 8 + r], s, L);
            }
        }
#pragma unroll
        for (int o = 16; o > 0; o >>= 1) L += __shfl_xor_sync(0xffffffffu, L, o);
        if (lane == 0) stage[0][w] = L;
        __syncthreads();
        if (tid == 0) {
            float s2 = 0.0f;
#pragma unroll
            for (int i = 0; i < 8; ++i) s2 += stage[0][i];
            atomicAdd(out, s2 * (0.1f / (float)NB));
        }
    }
}

// ---------------------------------------------------------------------------
extern "C" void kernel_launch(void* const* d_in, const int* in_sizes, int n_in,
                              void* d_out, int out_size) {
    const float4* D4 = reinterpret_cast<const float4*>(d_in[0]);
    float* out = reinterpret_cast<float*>(d_out);

    k_convert<<<16384, 256>>>(D4, out);
    k_sink<<<NB * GCTAS, 256>>>(out);
}

// round 10
// speedup vs baseline: 2.2320x; 1.2114x over previous
#include <cuda_runtime.h>
#include <cuda_fp16.h>

#define NB 32
#define NN 1024
#define NM 1024
#define CSH8 6.104793232414985f   /* ln(448) */
#define GCTAS 16                  /* CTAs per batch-group */
#define NITER 20
#define USCALE 32768.0f           /* keeps u in fp16-normal range */

// K'' = 448*exp(-D/eps) as e4m3 fp8. 32 MB — L2-resident.
__device__ unsigned char g_K8[(size_t)NB * NN * NM];
__device__ float g_t[3][NB * NM];            // scaled col-sum triple buffer
__device__ unsigned g_bar[NB * 32];          // per-batch epoch counter

// ---- fp8 / fp16 helpers -----------------------------------------------------
__device__ __forceinline__ unsigned short pack_e4m3x2(float lo, float hi) {
    unsigned short r;
    asm("cvt.rn.satfinite.e4m3x2.f32 %0, %1, %2;" : "=h"(r) : "f"(hi), "f"(lo));
    return r;
}
// 4 packed e4m3 -> 2 half2 (exact)
__device__ __forceinline__ void e4m3x4_to_h2(unsigned w, __half2& A, __half2& B) {
    unsigned h0, h1;
    asm("{\n\t.reg .b16 a, b;\n\t"
        "mov.b32 {a, b}, %2;\n\t"
        "cvt.rn.f16x2.e4m3x2 %0, a;\n\t"
        "cvt.rn.f16x2.e4m3x2 %1, b;\n\t}"
        : "=r"(h0), "=r"(h1) : "r"(w));
    A = *reinterpret_cast<__half2*>(&h0);
    B = *reinterpret_cast<__half2*>(&h1);
}
__device__ __forceinline__ float4 e4m3x4_to_float4(unsigned int w) {
    __half2 A, B;
    e4m3x4_to_h2(w, A, B);
    float2 f0 = __half22float2(A);
    float2 f1 = __half22float2(B);
    return make_float4(f0.x, f0.y, f1.x, f1.y);
}
// 16 fp8 x 16 fp16 v values -> f32 (one fp16 chain of 8 HFMA2, widened once)
__device__ __forceinline__ float dot16h(uint4 p, const __half2* vv) {
    __half2 acc = __float2half2_rn(0.0f);
    __half2 k0, k1, k2, k3, k4, k5, k6, k7;
    e4m3x4_to_h2(p.x, k0, k1);
    e4m3x4_to_h2(p.y, k2, k3);
    e4m3x4_to_h2(p.z, k4, k5);
    e4m3x4_to_h2(p.w, k6, k7);
    acc = __hfma2(k0, vv[0], acc);
    acc = __hfma2(k1, vv[1], acc);
    acc = __hfma2(k2, vv[2], acc);
    acc = __hfma2(k3, vv[3], acc);
    acc = __hfma2(k4, vv[4], acc);
    acc = __hfma2(k5, vv[5], acc);
    acc = __hfma2(k6, vv[6], acc);
    acc = __hfma2(k7, vv[7], acc);
    float2 f = __half22float2(acc);
    return f.x + f.y;
}

// CG-style 16-CTA epoch barrier: monotonic counter, no reset races.
__device__ __forceinline__ void group_barrier(unsigned* bar, unsigned target) {
    __syncthreads();
    if (threadIdx.x == 0) {
        asm volatile("fence.acq_rel.gpu;" ::: "memory");
        unsigned prev = atomicAdd(bar, 1u);
        if (prev + 1u < target) {
            unsigned v;
            do {
                asm volatile("ld.acquire.gpu.u32 %0, [%1];"
                             : "=r"(v) : "l"(bar) : "memory");
            } while (v < target);
        }
    }
    __syncthreads();
}

// ---------------------------------------------------------------------------
// Convert: K8 = e4m3(448*exp(-10D)); t[0]=USCALE (v0=1), t[1]=0, bar=0, out=0.
// ---------------------------------------------------------------------------
__global__ __launch_bounds__(256) void k_convert(const float4* __restrict__ D4,
                                                 float* __restrict__ out) {
    int idx = blockIdx.x * 256 + threadIdx.x;      // 0 .. 4194303
    float4 d0 = D4[2 * idx];
    float4 d1 = D4[2 * idx + 1];
    float e0 = __expf(fmaf(d0.x, -10.0f, CSH8));
    float e1 = __expf(fmaf(d0.y, -10.0f, CSH8));
    float e2 = __expf(fmaf(d0.z, -10.0f, CSH8));
    float e3 = __expf(fmaf(d0.w, -10.0f, CSH8));
    float e4 = __expf(fmaf(d1.x, -10.0f, CSH8));
    float e5 = __expf(fmaf(d1.y, -10.0f, CSH8));
    float e6 = __expf(fmaf(d1.z, -10.0f, CSH8));
    float e7 = __expf(fmaf(d1.w, -10.0f, CSH8));
    unsigned short p0 = pack_e4m3x2(e0, e1);
    unsigned short p1 = pack_e4m3x2(e2, e3);
    unsigned short p2 = pack_e4m3x2(e4, e5);
    unsigned short p3 = pack_e4m3x2(e6, e7);
    uint2 w;
    w.x = (unsigned int)p0 | ((unsigned int)p1 << 16);
    w.y = (unsigned int)p2 | ((unsigned int)p3 << 16);
    reinterpret_cast<uint2*>(g_K8)[idx] = w;

    if (idx < NB * NM) { g_t[0][idx] = USCALE; g_t[1][idx] = 0.0f; }
    if (idx < NB * 32) g_bar[idx] = 0u;
    if (idx == 0) *out = 0.0f;
}

// ---------------------------------------------------------------------------
// Persistent Sinkhorn: grid 512 = 32 batches x 16 CTAs; CTA owns 64 rows.
// fp16 HFMA2 inner loops; u scaled by USCALE to stay fp16-normal.
// ---------------------------------------------------------------------------
__global__ __launch_bounds__(256, 4) void k_sink(float* __restrict__ out) {
    __shared__ __half2 vh[NM / 2];       // 2 KB : v as packed half2
    __shared__ float   Uf[64];           // u (f32, for final loss)
    __shared__ __half  Uh[64];           // u' = USCALE*u (fp16, col phase)
    __shared__ float   stage[4][NM];     // 16 KB : col merge / final-v scratch
    __shared__ float   lpart[8];

    int tid  = threadIdx.x;
    int w    = tid >> 5, lane = tid & 31;
    int b    = blockIdx.x >> 4;          // batch
    int rc   = blockIdx.x & 15;          // rows [rc*64, rc*64+64)
    unsigned* bar = &g_bar[b * 32];

    const unsigned char* Kcta = g_K8 + ((size_t)b * NN + rc * 64) * NM;

    for (int it = 0; it < NITER; ++it) {
        const float* tIn  = g_t[it % 3] + b * NM;
        float* tOut       = g_t[(it + 1) % 3] + b * NM;
        float* tZero      = g_t[(it + 2) % 3] + b * NM;

        // ---- row phase: s_i = sum_j K_ij v_j ; u = 1/s ----------------------
        {
            float4 t4 = reinterpret_cast<const float4*>(tIn)[tid];
            float v0 = __fdividef(USCALE, t4.x);
            float v1 = __fdividef(USCALE, t4.y);
            float v2 = __fdividef(USCALE, t4.z);
            float v3 = __fdividef(USCALE, t4.w);
            vh[2 * tid]     = __floats2half2_rn(v0, v1);
            vh[2 * tid + 1] = __floats2half2_rn(v2, v3);
            if (tid < 64) tZero[rc * 64 + tid] = 0.0f;
            __syncthreads();

            const uint4* Kr = reinterpret_cast<const uint4*>(Kcta + (size_t)w * 8 * NM);
            const uint4* vhu = reinterpret_cast<const uint4*>(vh);
            float acc[8];
#pragma unroll
            for (int r = 0; r < 8; ++r) acc[r] = 0.0f;
#pragma unroll
            for (int ph = 0; ph < 2; ++ph) {
                int q = ph * 32 + lane;                  // uint4 idx 0..63
                __half2 vv[8];
                uint4 va = vhu[2 * q];
                uint4 vb = vhu[2 * q + 1];
                vv[0] = *reinterpret_cast<__half2*>(&va.x);
                vv[1] = *reinterpret_cast<__half2*>(&va.y);
                vv[2] = *reinterpret_cast<__half2*>(&va.z);
                vv[3] = *reinterpret_cast<__half2*>(&va.w);
                vv[4] = *reinterpret_cast<__half2*>(&vb.x);
                vv[5] = *reinterpret_cast<__half2*>(&vb.y);
                vv[6] = *reinterpret_cast<__half2*>(&vb.z);
                vv[7] = *reinterpret_cast<__half2*>(&vb.w);
#pragma unroll
                for (int r = 0; r < 8; ++r)
                    acc[r] += dot16h(Kr[r * 64 + q], vv);
            }
#pragma unroll
            for (int r = 0; r < 8; ++r) {
                float s = acc[r];
#pragma unroll
                for (int o = 16; o > 0; o >>= 1)
                    s += __shfl_xor_sync(0xffffffffu, s, o);
                if (lane == 0) {
                    float u = __fdividef(1.0f, s);
                    Uf[w * 8 + r] = u;
                    Uh[w * 8 + r] = __float2half(USCALE * u);
                }
            }
            __syncthreads();
        }

        // ---- col phase: t'_j += sum_i K_ij u'_i -----------------------------
        {
            int cg = tid >> 6, ct = tid & 63;
            const uint4* Kb =
                reinterpret_cast<const uint4*>(Kcta + (size_t)cg * 16 * NM) + ct;
            __half2 C[8];
#pragma unroll
            for (int m = 0; m < 8; ++m) C[m] = __float2half2_rn(0.0f);
#pragma unroll
            for (int i = 0; i < 16; ++i) {
                __half2 u2 = __half2half2(Uh[cg * 16 + i]);
                uint4 p = Kb[i * (NM / 16)];
                __half2 k0, k1, k2, k3, k4, k5, k6, k7;
                e4m3x4_to_h2(p.x, k0, k1);
                e4m3x4_to_h2(p.y, k2, k3);
                e4m3x4_to_h2(p.z, k4, k5);
                e4m3x4_to_h2(p.w, k6, k7);
                C[0] = __hfma2(k0, u2, C[0]);
                C[1] = __hfma2(k1, u2, C[1]);
                C[2] = __hfma2(k2, u2, C[2]);
                C[3] = __hfma2(k3, u2, C[3]);
                C[4] = __hfma2(k4, u2, C[4]);
                C[5] = __hfma2(k5, u2, C[5]);
                C[6] = __hfma2(k6, u2, C[6]);
                C[7] = __hfma2(k7, u2, C[7]);
            }
            float2* st2 = reinterpret_cast<float2*>(&stage[cg][ct * 16]);
#pragma unroll
            for (int m = 0; m < 8; ++m) st2[m] = __half22float2(C[m]);
            __syncthreads();

            const float4* s0 = reinterpret_cast<const float4*>(stage[0]);
            const float4* s1 = reinterpret_cast<const float4*>(stage[1]);
            const float4* s2 = reinterpret_cast<const float4*>(stage[2]);
            const float4* s3 = reinterpret_cast<const float4*>(stage[3]);
            float4 r0 = s0[tid], r1 = s1[tid], r2 = s2[tid], r3 = s3[tid];
            float4 r;
            r.x = (r0.x + r1.x) + (r2.x + r3.x);
            r.y = (r0.y + r1.y) + (r2.y + r3.y);
            r.z = (r0.z + r1.z) + (r2.z + r3.z);
            r.w = (r0.w + r1.w) + (r2.w + r3.w);
            float* to = tOut + tid * 4;
            atomicAdd(to + 0, r.x);
            atomicAdd(to + 1, r.y);
            atomicAdd(to + 2, r.z);
            atomicAdd(to + 3, r.w);
            __syncthreads();   // stage reused next iter / final
        }

        // ---- group barrier (epoch it+1) -------------------------------------
        group_barrier(bar, (unsigned)(GCTAS * (it + 1)));
    }

    // ---- loss (f32): (0.1/NB) sum u_i v_j f (ln448 - ln f) -------------------
    {
        const float* tIn = g_t[(NITER + 1) % 3] + b * NM;   // t[0]: (19+2)%3... final tOut = t[(19+1)%3] = t[2]
        tIn = g_t[2] + b * NM;
        float4* svf = reinterpret_cast<float4*>(stage[0]);  // reuse scratch
        float4 t4 = reinterpret_cast<const float4*>(tIn)[tid];
        svf[tid] = make_float4(__fdividef(USCALE, t4.x), __fdividef(USCALE, t4.y),
                               __fdividef(USCALE, t4.z), __fdividef(USCALE, t4.w));
        __syncthreads();

        const uint4* Kr = reinterpret_cast<const uint4*>(Kcta + (size_t)w * 8 * NM);
        float L = 0.0f;
#pragma unroll
        for (int ph = 0; ph < 2; ++ph) {
            int q = ph * 32 + lane;
            float4 v0 = svf[4 * q + 0];
            float4 v1 = svf[4 * q + 1];
            float4 v2 = svf[4 * q + 2];
            float4 v3 = svf[4 * q + 3];
#pragma unroll
            for (int r = 0; r < 8; ++r) {
                uint4 p = Kr[r * 64 + q];
                float4 a = e4m3x4_to_float4(p.x);
                float4 bb = e4m3x4_to_float4(p.y);
                float4 c = e4m3x4_to_float4(p.z);
                float4 d = e4m3x4_to_float4(p.w);
                float s = 0.0f;
                s = fmaf(a.x  * (CSH8 - __logf(a.x)),  v0.x, s);
                s = fmaf(a.y  * (CSH8 - __logf(a.y)),  v0.y, s);
                s = fmaf(a.z  * (CSH8 - __logf(a.z)),  v0.z, s);
                s = fmaf(a.w  * (CSH8 - __logf(a.w)),  v0.w, s);
                s = fmaf(bb.x * (CSH8 - __logf(bb.x)), v1.x, s);
                s = fmaf(bb.y * (CSH8 - __logf(bb.y)), v1.y, s);
                s = fmaf(bb.z * (CSH8 - __logf(bb.z)), v1.z, s);
                s = fmaf(bb.w * (CSH8 - __logf(bb.w)), v1.w, s);
                s = fmaf(c.x  * (CSH8 - __logf(c.x)),  v2.x, s);
                s = fmaf(c.y  * (CSH8 - __logf(c.y)),  v2.y, s);
                s = fmaf(c.z  * (CSH8 - __logf(c.z)),  v2.z, s);
                s = fmaf(c.w  * (CSH8 - __logf(c.w)),  v2.w, s);
                s = fmaf(d.x  * (CSH8 - __logf(d.x)),  v3.x, s);
                s = fmaf(d.y  * (CSH8 - __logf(d.y)),  v3.y, s);
                s = fmaf(d.z  * (CSH8 - __logf(d.z)),  v3.z, s);
                s = fmaf(d.w  * (CSH8 - __logf(d.w)),  v3.w, s);
                L = fmaf(Uf[w * 8 + r], s, L);
            }
        }
#pragma unroll
        for (int o = 16; o > 0; o >>= 1) L += __shfl_xor_sync(0xffffffffu, L, o);
        if (lane == 0) lpart[w] = L;
        __syncthreads();
        if (tid == 0) {
            float s2 = 0.0f;
#pragma unroll
            for (int i = 0; i < 8; ++i) s2 += lpart[i];
            atomicAdd(out, s2 * (0.1f / (float)NB));
        }
    }
}

// ---------------------------------------------------------------------------
extern "C" void kernel_launch(void* const* d_in, const int* in_sizes, int n_in,
                              void* d_out, int out_size) {
    const float4* D4 = reinterpret_cast<const float4*>(d_in[0]);
    float* out = reinterpret_cast<float*>(d_out);

    k_convert<<<16384, 256>>>(D4, out);
    k_sink<<<NB * GCTAS, 256>>>(out);
}